// round 3
// baseline (speedup 1.0000x reference)
#include <cuda_runtime.h>
#include <cuda_bf16.h>
#include <math.h>

// Problem constants
#define B  2
#define N  512
#define FI 256
#define FO 128
#define ALPHA 0.2f

// e-kernel tiling
#define TJ 32
#define TI 32
#define NPART (B * (N/TI) * (N/TJ))   // 2*16*16 = 512

// output-kernel tiling
#define ROWS_D 8                       // rows per CTA in final kernel

// Scratch (no allocations allowed -> device globals)
__device__ float g_Wh[B * N * FO];     // 512 KB
__device__ float g_e [B * N * N];      // 2 MB
__device__ float g_part[NPART];
__device__ float g_inv[1];

__device__ __forceinline__ float lrelu(float x) {
    // alpha < 1: max(x, alpha*x) == leaky_relu(x)
    return fmaxf(x, ALPHA * x);
}

// ---------------------------------------------------------------------------
// Kernel A: Wh = x @ W      grid: B*N blocks, 128 threads (one output o each)
// ---------------------------------------------------------------------------
__global__ void k_gemm(const float* __restrict__ x, const float* __restrict__ W) {
    const int row = blockIdx.x;          // 0 .. B*N-1
    const int o   = threadIdx.x;         // 0 .. 127

    __shared__ float xs[FI];
    #pragma unroll
    for (int f = threadIdx.x; f < FI; f += FO)
        xs[f] = x[row * FI + f];
    __syncthreads();

    float acc = 0.f;
    #pragma unroll 8
    for (int f = 0; f < FI; f++)
        acc = fmaf(xs[f], W[f * FO + o], acc);

    g_Wh[row * FO + o] = acc;
}

// ---------------------------------------------------------------------------
// Kernel B: e[b,i,j] = sum_o a_o * lrelu(Wh[b,i,o] + Wh[b,j,o])
//           + per-block partial sum of e^2 (for the global norm)
// grid: (N/TJ, N/TI, B), block: (32, 8) -> each thread does 4 i's, 1 j
// ---------------------------------------------------------------------------
__global__ void k_edges(const float* __restrict__ a_fc) {
    const int b  = blockIdx.z;
    const int it = blockIdx.y * TI;
    const int jt = blockIdx.x * TJ;
    const int tx = threadIdx.x;          // j lane 0..31
    const int ty = threadIdx.y;          // 0..7
    const int tid = ty * 32 + tx;

    // padded float4 tiles: row stride 33 float4 (=132 floats) -> conflict free
    __shared__ float4 tIs[TI * 33];
    __shared__ float4 tJs[TJ * 33];
    __shared__ float4 aS[FO / 4];

    const float4* Wh4 = reinterpret_cast<const float4*>(g_Wh);
    const float4* a4  = reinterpret_cast<const float4*>(a_fc);

    if (tid < FO / 4) aS[tid] = a4[tid];

    // load both 32x128 tiles (32 rows x 32 float4 each)
    #pragma unroll
    for (int p = 0; p < 4; p++) {
        int idx = tid + 256 * p;         // 0..1023
        int r = idx >> 5, c = idx & 31;
        tIs[r * 33 + c] = Wh4[(b * N + it + r) * (FO / 4) + c];
        tJs[r * 33 + c] = Wh4[(b * N + jt + r) * (FO / 4) + c];
    }
    __syncthreads();

    float acc[4] = {0.f, 0.f, 0.f, 0.f};

    #pragma unroll 4
    for (int oc = 0; oc < FO / 4; oc++) {
        const float4 wj = tJs[tx * 33 + oc];    // lane-varying, conflict-free
        const float4 av = aS[oc];               // broadcast
        #pragma unroll
        for (int k = 0; k < 4; k++) {
            const float4 wi = tIs[(ty + 8 * k) * 33 + oc];  // warp broadcast
            float s;
            s = acc[k];
            s = fmaf(lrelu(wi.x + wj.x), av.x, s);
            s = fmaf(lrelu(wi.y + wj.y), av.y, s);
            s = fmaf(lrelu(wi.z + wj.z), av.z, s);
            s = fmaf(lrelu(wi.w + wj.w), av.w, s);
            acc[k] = s;
        }
    }

    float ss = 0.f;
    #pragma unroll
    for (int k = 0; k < 4; k++) {
        const int i = it + ty + 8 * k;
        g_e[(b * N + i) * N + jt + tx] = acc[k];
        ss = fmaf(acc[k], acc[k], ss);
    }

    // deterministic block reduction of ss
    #pragma unroll
    for (int off = 16; off > 0; off >>= 1)
        ss += __shfl_xor_sync(0xFFFFFFFFu, ss, off);

    __shared__ float wsum[8];
    if (tx == 0) wsum[ty] = ss;
    __syncthreads();
    if (tid == 0) {
        float t = 0.f;
        #pragma unroll
        for (int w = 0; w < 8; w++) t += wsum[w];
        g_part[(blockIdx.z * (N/TI) + blockIdx.y) * (N/TJ) + blockIdx.x] = t;
    }
}

// ---------------------------------------------------------------------------
// Kernel C: reduce partials -> g_inv = 1/sqrt(sum e^2)   (deterministic tree)
// ---------------------------------------------------------------------------
__global__ void k_norm() {
    __shared__ float sm[NPART];
    const int t = threadIdx.x;
    sm[t] = g_part[t];
    __syncthreads();
    #pragma unroll
    for (int s = NPART / 2; s > 0; s >>= 1) {
        if (t < s) sm[t] += sm[t + s];
        __syncthreads();
    }
    if (t == 0) g_inv[0] = 1.0f / sqrtf(sm[0]);
}

// ---------------------------------------------------------------------------
// Kernel D: per-row mask + softmax, then h' = att @ Wh, then ELU
// grid: (N/ROWS_D, B), block: (128, 2)
//   phase 1: 8 warps, one row each -> unnormalized exp weights in smem
//   phase 2: thread (o=tx, ty) accumulates 4 rows over all j
// ---------------------------------------------------------------------------
__global__ void k_out(const int* __restrict__ adj, float* __restrict__ out) {
    const int b  = blockIdx.y;
    const int i0 = blockIdx.x * ROWS_D;
    const int tx = threadIdx.x;
    const int ty = threadIdx.y;
    const int tid  = ty * 128 + tx;
    const int warp = tid >> 5;
    const int lane = tid & 31;

    __shared__ float att[ROWS_D][N];   // unnormalized softmax weights
    __shared__ float rnorm[ROWS_D];    // 1/rowsum

    const float inv = g_inv[0];

    // ---- phase 1: softmax weights for row (i0 + warp) ----
    {
        const int i = i0 + warp;
        const float* erow = &g_e[(b * N + i) * N];
        const int*   arow = &adj[(b * N + i) * N];

        float ev[N / 32];
        float mx = -INFINITY;
        #pragma unroll
        for (int m = 0; m < N / 32; m++) {
            const int j = lane + 32 * m;
            float v = erow[j] * inv;
            if (arow[j] == 0) v = -INFINITY;
            ev[m] = v;
            mx = fmaxf(mx, v);
        }
        #pragma unroll
        for (int off = 16; off > 0; off >>= 1)
            mx = fmaxf(mx, __shfl_xor_sync(0xFFFFFFFFu, mx, off));

        float sum = 0.f;
        #pragma unroll
        for (int m = 0; m < N / 32; m++) {
            const int j = lane + 32 * m;
            const float p = expf(ev[m] - mx);   // exp(-inf)=0 for masked
            att[warp][j] = p;
            sum += p;
        }
        #pragma unroll
        for (int off = 16; off > 0; off >>= 1)
            sum += __shfl_xor_sync(0xFFFFFFFFu, sum, off);
        if (lane == 0) rnorm[warp] = 1.0f / sum;
    }
    __syncthreads();

    // ---- phase 2: h'[i, o] = sum_j att[i][j] * Wh[b, j, o] ----
    const int r0 = ty * 4;
    const int o  = tx;
    float acc[4] = {0.f, 0.f, 0.f, 0.f};

    const float* WhB = &g_Wh[b * N * FO];
    const float4 (*att4)[N / 4] = reinterpret_cast<const float4 (*)[N / 4]>(att);

    #pragma unroll 4
    for (int jc = 0; jc < N / 4; jc++) {
        const int j = jc * 4;
        const float w0 = WhB[(j + 0) * FO + o];
        const float w1 = WhB[(j + 1) * FO + o];
        const float w2 = WhB[(j + 2) * FO + o];
        const float w3 = WhB[(j + 3) * FO + o];
        #pragma unroll
        for (int r = 0; r < 4; r++) {
            const float4 a4 = att4[r0 + r][jc];   // warp broadcast
            float s = acc[r];
            s = fmaf(a4.x, w0, s);
            s = fmaf(a4.y, w1, s);
            s = fmaf(a4.z, w2, s);
            s = fmaf(a4.w, w3, s);
            acc[r] = s;
        }
    }

    #pragma unroll
    for (int r = 0; r < 4; r++) {
        const int i = i0 + r0 + r;
        float v = acc[r] * rnorm[r0 + r];
        v = (v > 0.f) ? v : expm1f(v);          // ELU (alpha=1)
        out[(b * N + i) * FO + o] = v;
    }
}

// ---------------------------------------------------------------------------
extern "C" void kernel_launch(void* const* d_in, const int* in_sizes, int n_in,
                              void* d_out, int out_size) {
    const float* x    = (const float*)d_in[0];   // [B,N,FI]
    const int*   adj  = (const int*)  d_in[1];   // [B,N,N]
    const float* W    = (const float*)d_in[2];   // [FI,FO]
    const float* a_fc = (const float*)d_in[3];   // [FO]
    float* out = (float*)d_out;                  // [B,N,FO]

    k_gemm <<< B * N, FO >>>(x, W);
    k_edges<<< dim3(N/TJ, N/TI, B), dim3(32, 8) >>>(a_fc);
    k_norm <<< 1, NPART >>>();
    k_out  <<< dim3(N/ROWS_D, B), dim3(128, 2) >>>(adj, out);
}

// round 4
// speedup vs baseline: 1.1309x; 1.1309x over previous
#include <cuda_runtime.h>
#include <cuda_bf16.h>
#include <math.h>

// Problem constants
#define B  2
#define N  512
#define FI 256
#define FO 128
#define ALPHA 0.2f

// e-kernel tiling
#define TJ 32
#define TI 32
#define NPART (B * (N/TI) * (N/TJ))   // 512

// GEMM (att @ Wh) tiling
#define MT 32          // i-rows per CTA
#define KC 128         // j-chunk per CTA (split-K)
#define KT 32          // smem sub-tile depth
#define NCHUNK (N/KC)  // 4

typedef unsigned long long ull;

// Scratch (no allocations allowed -> device globals)
__device__ float g_Wh[B * N * FO];        // 512 KB
__device__ float g_e [B * N * N];         // 2 MB (e, then normalized att in-place)
__device__ float g_c [B * N];             // ci = sum_o a_o * Wh[i,o]
__device__ float g_part[NPART];
__device__ float g_inv[1];
__device__ float g_pt[NCHUNK][B * N * FO]; // split-K partials, 2 MB

__device__ __forceinline__ ull fadd2(ull a, ull b) {
    ull d; asm("add.rn.f32x2 %0, %1, %2;" : "=l"(d) : "l"(a), "l"(b)); return d;
}
__device__ __forceinline__ ull ffma2(ull a, ull b, ull c) {
    ull d; asm("fma.rn.f32x2 %0, %1, %2, %3;" : "=l"(d) : "l"(a), "l"(b), "l"(c)); return d;
}
__device__ __forceinline__ float lo_f(ull v) { return __uint_as_float((unsigned)(v & 0xFFFFFFFFull)); }
__device__ __forceinline__ float hi_f(ull v) { return __uint_as_float((unsigned)(v >> 32)); }

#define ABS2_MASK 0x7FFFFFFF7FFFFFFFull

// ---------------------------------------------------------------------------
// Kernel A: Wh = x @ W  (+ ci = Wh . a_fc)
// grid: B*N/4, block: 128.  thread: row r = tx>>5 (4 rows/CTA), o4 = tx&31.
// ---------------------------------------------------------------------------
__global__ void k_gemm(const float* __restrict__ x, const float* __restrict__ W,
                       const float* __restrict__ a_fc) {
    const int row0 = blockIdx.x * 4;
    const int tx   = threadIdx.x;
    const int r    = tx >> 5;
    const int lane = tx & 31;

    __shared__ float xs[4][FI];
    {
        const float4* x4 = reinterpret_cast<const float4*>(x + row0 * FI);
        float4* xs4 = reinterpret_cast<float4*>(&xs[0][0]);
        xs4[tx]       = x4[tx];
        xs4[tx + 128] = x4[tx + 128];
    }
    __syncthreads();

    const float4* W4 = reinterpret_cast<const float4*>(W);   // [FI][FO/4]
    float4 acc = make_float4(0.f, 0.f, 0.f, 0.f);

    #pragma unroll 8
    for (int f = 0; f < FI; f++) {
        const float4 w = W4[f * (FO/4) + lane];
        const float xv = xs[r][f];
        acc.x = fmaf(xv, w.x, acc.x);
        acc.y = fmaf(xv, w.y, acc.y);
        acc.z = fmaf(xv, w.z, acc.z);
        acc.w = fmaf(xv, w.w, acc.w);
    }

    reinterpret_cast<float4*>(g_Wh)[(row0 + r) * (FO/4) + lane] = acc;

    // ci = sum_o a_o * Wh[row, o]   (warp covers all o for its row)
    const float4 av = reinterpret_cast<const float4*>(a_fc)[lane];
    float m = acc.x * av.x + acc.y * av.y + acc.z * av.z + acc.w * av.w;
    #pragma unroll
    for (int off = 16; off > 0; off >>= 1)
        m += __shfl_xor_sync(0xFFFFFFFFu, m, off);
    if (lane == 0) g_c[row0 + r] = m;
}

// ---------------------------------------------------------------------------
// Kernel B: e[b,i,j] = 0.6*(ci+cj) + 0.4 * sum_o a_o * |Wh_i,o + Wh_j,o|
//           (identical to sum_o a_o*lrelu(.) since lrelu(s)=0.6s+0.4|s|)
//           + per-block partial sum of e^2
// grid: (N/TJ, N/TI, B), block: (32, 8) -> each thread 4 i's, 1 j
// ---------------------------------------------------------------------------
__global__ void k_edges(const float* __restrict__ a_fc) {
    const int b  = blockIdx.z;
    const int it = blockIdx.y * TI;
    const int jt = blockIdx.x * TJ;
    const int tx = threadIdx.x;
    const int ty = threadIdx.y;
    const int tid = ty * 32 + tx;

    __shared__ float4 tIs[TI * 33];
    __shared__ float4 tJs[TJ * 33];
    __shared__ float4 aS[FO / 4];
    __shared__ float  cIs[TI];
    __shared__ float  cJs[TJ];

    const float4* Wh4 = reinterpret_cast<const float4*>(g_Wh);
    const float4* a4  = reinterpret_cast<const float4*>(a_fc);

    if (tid < FO / 4) aS[tid] = a4[tid];
    if (tid >= 64 && tid < 96)  cIs[tid - 64] = 0.6f * g_c[b * N + it + (tid - 64)];
    if (tid >= 96 && tid < 128) cJs[tid - 96] = 0.6f * g_c[b * N + jt + (tid - 96)];

    #pragma unroll
    for (int p = 0; p < 4; p++) {
        int idx = tid + 256 * p;
        int r = idx >> 5, c = idx & 31;
        tIs[r * 33 + c] = Wh4[(b * N + it + r) * (FO / 4) + c];
        tJs[r * 33 + c] = Wh4[(b * N + jt + r) * (FO / 4) + c];
    }
    __syncthreads();

    const ulonglong2* tI2 = reinterpret_cast<const ulonglong2*>(tIs);
    const ulonglong2* tJ2 = reinterpret_cast<const ulonglong2*>(tJs);
    const ulonglong2* a2  = reinterpret_cast<const ulonglong2*>(aS);

    ull accA[4] = {0, 0, 0, 0};
    ull accB[4] = {0, 0, 0, 0};

    #pragma unroll 4
    for (int oc = 0; oc < FO / 4; oc++) {
        const ulonglong2 wj = tJ2[tx * 33 + oc];       // lane-varying
        const ulonglong2 av = a2[oc];                  // broadcast
        #pragma unroll
        for (int k = 0; k < 4; k++) {
            const ulonglong2 wi = tI2[(ty + 8 * k) * 33 + oc];  // warp broadcast
            ull s0 = fadd2(wi.x, wj.x) & ABS2_MASK;
            ull s1 = fadd2(wi.y, wj.y) & ABS2_MASK;
            accA[k] = ffma2(s0, av.x, accA[k]);
            accB[k] = ffma2(s1, av.y, accB[k]);
        }
    }

    float ss = 0.f;
    const float cj = cJs[tx];
    #pragma unroll
    for (int k = 0; k < 4; k++) {
        const ull t = fadd2(accA[k], accB[k]);
        const float absSum = lo_f(t) + hi_f(t);
        const float e = fmaf(0.4f, absSum, cIs[ty + 8 * k] + cj);
        const int i = it + ty + 8 * k;
        g_e[(b * N + i) * N + jt + tx] = e;
        ss = fmaf(e, e, ss);
    }

    #pragma unroll
    for (int off = 16; off > 0; off >>= 1)
        ss += __shfl_xor_sync(0xFFFFFFFFu, ss, off);

    __shared__ float wsum[8];
    if (tx == 0) wsum[ty] = ss;
    __syncthreads();
    if (tid == 0) {
        float t = 0.f;
        #pragma unroll
        for (int w = 0; w < 8; w++) t += wsum[w];
        g_part[(blockIdx.z * (N/TI) + blockIdx.y) * (N/TJ) + blockIdx.x] = t;
    }
}

// ---------------------------------------------------------------------------
// Kernel C: reduce partials -> g_inv = 1/sqrt(sum e^2)
// ---------------------------------------------------------------------------
__global__ void k_norm() {
    __shared__ float sm[NPART];
    const int t = threadIdx.x;
    sm[t] = g_part[t];
    __syncthreads();
    #pragma unroll
    for (int s = NPART / 2; s > 0; s >>= 1) {
        if (t < s) sm[t] += sm[t + s];
        __syncthreads();
    }
    if (t == 0) g_inv[0] = 1.0f / sqrtf(sm[0]);
}

// ---------------------------------------------------------------------------
// Kernel S: per-row mask + softmax; writes NORMALIZED attention in-place to g_e
// grid: B*N/4, block: 128 (one warp per row)
// ---------------------------------------------------------------------------
__global__ void k_soft(const int* __restrict__ adj) {
    const int warp = threadIdx.x >> 5;
    const int lane = threadIdx.x & 31;
    const int row  = blockIdx.x * 4 + warp;       // global (b*N + i)

    const float inv = g_inv[0];
    float4* erow = reinterpret_cast<float4*>(g_e + row * N);
    const int4* arow = reinterpret_cast<const int4*>(adj + row * N);

    float4 ev[4];
    float mx = -INFINITY;
    #pragma unroll
    for (int m = 0; m < 4; m++) {
        const int c = lane + 32 * m;
        const float4 e4 = erow[c];
        const int4  a4 = arow[c];
        float4 v;
        v.x = (a4.x == 0) ? -INFINITY : e4.x * inv;
        v.y = (a4.y == 0) ? -INFINITY : e4.y * inv;
        v.z = (a4.z == 0) ? -INFINITY : e4.z * inv;
        v.w = (a4.w == 0) ? -INFINITY : e4.w * inv;
        ev[m] = v;
        mx = fmaxf(mx, fmaxf(fmaxf(v.x, v.y), fmaxf(v.z, v.w)));
    }
    #pragma unroll
    for (int off = 16; off > 0; off >>= 1)
        mx = fmaxf(mx, __shfl_xor_sync(0xFFFFFFFFu, mx, off));

    float sum = 0.f;
    #pragma unroll
    for (int m = 0; m < 4; m++) {
        float4 v = ev[m];
        v.x = __expf(v.x - mx);
        v.y = __expf(v.y - mx);
        v.z = __expf(v.z - mx);
        v.w = __expf(v.w - mx);
        ev[m] = v;
        sum += (v.x + v.y) + (v.z + v.w);
    }
    #pragma unroll
    for (int off = 16; off > 0; off >>= 1)
        sum += __shfl_xor_sync(0xFFFFFFFFu, sum, off);
    const float rn = 1.0f / sum;

    #pragma unroll
    for (int m = 0; m < 4; m++) {
        float4 v = ev[m];
        v.x *= rn; v.y *= rn; v.z *= rn; v.w *= rn;
        erow[lane + 32 * m] = v;
    }
}

// ---------------------------------------------------------------------------
// Kernel M: split-K GEMM  partial[c] = att[:, chunk c] @ Wh[chunk c, :]
// grid: (N/MT, NCHUNK, B), block: 256. thread: ox=tx&31 (4 o's), iy=tx>>5 (4 i's)
// ---------------------------------------------------------------------------
__global__ void k_mm() {
    const int it = blockIdx.x * MT;
    const int jc = blockIdx.y * KC;
    const int b  = blockIdx.z;
    const int tx = threadIdx.x;
    const int ox = tx & 31;
    const int iy = tx >> 5;

    __shared__ float att_s[KT * 36];     // [k][i], stride 36 (pad, 16B-aligned rows)
    __shared__ float wh_s[KT][FO];       // [k][o]

    float acc[4][4] = {};

    for (int kt = 0; kt < KC; kt += KT) {
        // att tile, transposed: thread i=tx&31 loads 4 k's (float4 along j)
        {
            const int i  = tx & 31;
            const int kq = tx >> 5;
            const float4 a4 = *reinterpret_cast<const float4*>(
                g_e + (b * N + it + i) * N + jc + kt + kq * 4);
            att_s[(kq * 4 + 0) * 36 + i] = a4.x;
            att_s[(kq * 4 + 1) * 36 + i] = a4.y;
            att_s[(kq * 4 + 2) * 36 + i] = a4.z;
            att_s[(kq * 4 + 3) * 36 + i] = a4.w;
        }
        // Wh tile: 32 rows x 128 o
        {
            const int o4 = tx & 31;
            const int kr = tx >> 5;
            const float4* src = reinterpret_cast<const float4*>(
                g_Wh + (b * N + jc + kt) * FO);
            #pragma unroll
            for (int p = 0; p < 4; p++) {
                const int k = kr + 8 * p;
                reinterpret_cast<float4*>(&wh_s[k][0])[o4] = src[k * (FO/4) + o4];
            }
        }
        __syncthreads();

        #pragma unroll
        for (int k = 0; k < KT; k++) {
            const float4 a4 = *reinterpret_cast<const float4*>(&att_s[k * 36 + iy * 4]); // bcast
            const float4 w4 = *reinterpret_cast<const float4*>(&wh_s[k][ox * 4]);        // lane-var
            acc[0][0] = fmaf(a4.x, w4.x, acc[0][0]);
            acc[0][1] = fmaf(a4.x, w4.y, acc[0][1]);
            acc[0][2] = fmaf(a4.x, w4.z, acc[0][2]);
            acc[0][3] = fmaf(a4.x, w4.w, acc[0][3]);
            acc[1][0] = fmaf(a4.y, w4.x, acc[1][0]);
            acc[1][1] = fmaf(a4.y, w4.y, acc[1][1]);
            acc[1][2] = fmaf(a4.y, w4.z, acc[1][2]);
            acc[1][3] = fmaf(a4.y, w4.w, acc[1][3]);
            acc[2][0] = fmaf(a4.z, w4.x, acc[2][0]);
            acc[2][1] = fmaf(a4.z, w4.y, acc[2][1]);
            acc[2][2] = fmaf(a4.z, w4.z, acc[2][2]);
            acc[2][3] = fmaf(a4.z, w4.w, acc[2][3]);
            acc[3][0] = fmaf(a4.w, w4.x, acc[3][0]);
            acc[3][1] = fmaf(a4.w, w4.y, acc[3][1]);
            acc[3][2] = fmaf(a4.w, w4.z, acc[3][2]);
            acc[3][3] = fmaf(a4.w, w4.w, acc[3][3]);
        }
        __syncthreads();
    }

    float4* dst = reinterpret_cast<float4*>(g_pt[blockIdx.y]) + (b * N + it) * (FO/4);
    #pragma unroll
    for (int r = 0; r < 4; r++)
        dst[(iy * 4 + r) * (FO/4) + ox] =
            make_float4(acc[r][0], acc[r][1], acc[r][2], acc[r][3]);
}

// ---------------------------------------------------------------------------
// Kernel F: sum split-K partials (fixed order) + ELU
// grid: 256, block: 128 -> one float4 per thread
// ---------------------------------------------------------------------------
__global__ void k_fin(float* __restrict__ out) {
    const int idx = blockIdx.x * blockDim.x + threadIdx.x;   // float4 index
    const float4 p0 = reinterpret_cast<const float4*>(g_pt[0])[idx];
    const float4 p1 = reinterpret_cast<const float4*>(g_pt[1])[idx];
    const float4 p2 = reinterpret_cast<const float4*>(g_pt[2])[idx];
    const float4 p3 = reinterpret_cast<const float4*>(g_pt[3])[idx];
    float4 v;
    v.x = ((p0.x + p1.x) + p2.x) + p3.x;
    v.y = ((p0.y + p1.y) + p2.y) + p3.y;
    v.z = ((p0.z + p1.z) + p2.z) + p3.z;
    v.w = ((p0.w + p1.w) + p2.w) + p3.w;
    v.x = (v.x > 0.f) ? v.x : expm1f(v.x);
    v.y = (v.y > 0.f) ? v.y : expm1f(v.y);
    v.z = (v.z > 0.f) ? v.z : expm1f(v.z);
    v.w = (v.w > 0.f) ? v.w : expm1f(v.w);
    reinterpret_cast<float4*>(out)[idx] = v;
}

// ---------------------------------------------------------------------------
extern "C" void kernel_launch(void* const* d_in, const int* in_sizes, int n_in,
                              void* d_out, int out_size) {
    const float* x    = (const float*)d_in[0];   // [B,N,FI]
    const int*   adj  = (const int*)  d_in[1];   // [B,N,N]
    const float* W    = (const float*)d_in[2];   // [FI,FO]
    const float* a_fc = (const float*)d_in[3];   // [FO]
    float* out = (float*)d_out;                  // [B,N,FO]

    k_gemm <<< B * N / 4, 128 >>>(x, W, a_fc);
    k_edges<<< dim3(N/TJ, N/TI, B), dim3(32, 8) >>>(a_fc);
    k_norm <<< 1, NPART >>>();
    k_soft <<< B * N / 4, 128 >>>(adj);
    k_mm   <<< dim3(N/MT, NCHUNK, B), 256 >>>();
    k_fin  <<< 256, 128 >>>(out);
}